// round 13
// baseline (speedup 1.0000x reference)
#include <cuda_runtime.h>
#include <math.h>
#include <cstdint>

#define Bq   8
#define Nq   2048
#define Dq   1024
#define Eq   8
#define Hq   4096
#define CAP  320
#define NTOK (Bq*Nq)
#define OUT_MAIN ((size_t)NTOK*Dq)

// ---- scratch (round-5 set; d_eo doubles as gathered/rounded input 'ei' for phase 1) ----
__device__ int   d_meta[NTOK];
__device__ float d_g1[NTOK];
__device__ float d_g2[NTOK];
__device__ int   d_a1[NTOK];
__device__ int   d_a2[NTOK];
__device__ float d_proxy[Bq*Eq];
__device__ int   d_slotTok[Eq*Bq*CAP];
__device__ float d_h [(size_t)Eq*Bq*CAP*Hq];   // tf32-valued post-GELU hidden
__device__ float d_eo[(size_t)Eq*Bq*CAP*Dq];   // phase1: ei (tf32 gathered x); phase2: expert out

// ---------------- helpers ----------------
__device__ __forceinline__ uint32_t smem_u32(const void* p) {
    uint32_t a;
    asm("{ .reg .u64 t; cvta.to.shared.u64 t, %1; cvt.u32.u64 %0, t; }" : "=r"(a) : "l"(p));
    return a;
}
__device__ __forceinline__ uint32_t f2tf32(float x) {
    uint32_t r;
    asm("cvt.rna.tf32.f32 %0, %1;" : "=r"(r) : "f"(x));
    return r;
}
__device__ __forceinline__ float tf32v(float x) {
    return __uint_as_float(f2tf32(x));
}
__device__ __forceinline__ void mma_tf32(float* d, const uint32_t* a, const uint32_t* b) {
    asm volatile(
        "mma.sync.aligned.m16n8k8.row.col.f32.tf32.tf32.f32 "
        "{%0,%1,%2,%3}, {%4,%5,%6,%7}, {%8,%9}, {%0,%1,%2,%3};\n"
        : "+f"(d[0]), "+f"(d[1]), "+f"(d[2]), "+f"(d[3])
        : "r"(a[0]), "r"(a[1]), "r"(a[2]), "r"(a[3]), "r"(b[0]), "r"(b[1]));
}
__device__ __forceinline__ void ldsm4(uint32_t* r, uint32_t addr) {
    asm volatile("ldmatrix.sync.aligned.m8n8.x4.shared.b16 {%0,%1,%2,%3}, [%4];"
        : "=r"(r[0]), "=r"(r[1]), "=r"(r[2]), "=r"(r[3]) : "r"(addr));
}
__device__ __forceinline__ void cpa16(uint32_t dst, const float* src) {
    asm volatile("cp.async.cg.shared.global [%0], [%1], 16;" :: "r"(dst), "l"(src) : "memory");
}
#define CP_COMMIT() asm volatile("cp.async.commit_group;" ::: "memory")
#define CP_WAIT0()  asm volatile("cp.async.wait_group 0;" ::: "memory")

// ---------------- init ----------------
__global__ void init_kernel() {
    int t = threadIdx.x;
    if (t < Bq*Eq) d_proxy[t] = 0.f;
}

// ---------------- gating ----------------
__global__ __launch_bounds__(256) void gating_kernel(
    const float* __restrict__ x, const float* __restrict__ wg,
    const float* __restrict__ rnd)
{
    __shared__ float s_wg[Eq][Dq];
    __shared__ float s_proxy[Eq];
    int tid = threadIdx.x;
    for (int f = tid; f < Dq*Eq; f += 256) {
        int d = f >> 3, e = f & 7;
        s_wg[e][d] = wg[f];
    }
    if (tid < Eq) s_proxy[tid] = 0.f;
    __syncthreads();

    int warp = tid >> 5, lane = tid & 31;
    int tok  = blockIdx.x * 8 + warp;
    const float* xp = x + (size_t)tok * Dq;

    float acc[Eq];
    #pragma unroll
    for (int e = 0; e < Eq; ++e) acc[e] = 0.f;
    #pragma unroll 4
    for (int i = 0; i < Dq/32; ++i) {
        float xv = xp[i*32 + lane];
        #pragma unroll
        for (int e = 0; e < Eq; ++e) acc[e] += xv * s_wg[e][i*32 + lane];
    }
    #pragma unroll
    for (int off = 16; off; off >>= 1)
        #pragma unroll
        for (int e = 0; e < Eq; ++e)
            acc[e] += __shfl_down_sync(0xffffffffu, acc[e], off);

    if (lane == 0) {
        float mx = acc[0];
        #pragma unroll
        for (int e = 1; e < Eq; ++e) mx = fmaxf(mx, acc[e]);
        float raw[Eq]; float s = 0.f;
        #pragma unroll
        for (int e = 0; e < Eq; ++e) { raw[e] = expf(acc[e] - mx); s += raw[e]; }
        float inv = 1.f / s;
        #pragma unroll
        for (int e = 0; e < Eq; ++e) raw[e] *= inv;
        int i1 = 0; float g1 = raw[0];
        #pragma unroll
        for (int e = 1; e < Eq; ++e) if (raw[e] > g1) { g1 = raw[e]; i1 = e; }
        int i2 = -1; float g2 = -1.f;
        #pragma unroll
        for (int e = 0; e < Eq; ++e) if (e != i1 && raw[e] > g2) { g2 = raw[e]; i2 = e; }
        float denom = g1 + g2 + 1e-9f;
        float g1n = g1 / denom, g2n = g2 / denom;
        int keep2 = (rnd[tok] < (g2n / 0.2f)) ? 1 : 0;
        d_meta[tok] = i1 | (i2 << 4) | (keep2 << 8);
        d_g1[tok] = g1n;
        d_g2[tok] = g2n;
        #pragma unroll
        for (int e = 0; e < Eq; ++e) atomicAdd(&s_proxy[e], raw[e]);
    }
    __syncthreads();
    if (tid < Eq) {
        int b = (blockIdx.x * 8) >> 11;
        atomicAdd(&d_proxy[b*Eq + tid], s_proxy[tid]);
    }
}

// ---------------- scan ----------------
__global__ void scan_kernel(float* __restrict__ dout, int out_size)
{
    __shared__ int   s_meta[2048];
    __shared__ float s_red[64];
    int t = threadIdx.x;
    int b = t >> 3, e = t & 7;
    int g = e * Bq + b;
    for (int j = 0; j < CAP; ++j) d_slotTok[g*CAP + j] = -1;
    int c1 = 0;
    for (int ch = 0; ch < 8; ++ch) {
        __syncthreads();
        for (int i = t; i < 2048; i += 64) {
            int bb = i >> 8, ii = i & 255;
            s_meta[i] = d_meta[bb*Nq + ch*256 + ii];
        }
        __syncthreads();
        for (int ii = 0; ii < 256; ++ii) {
            int meta = s_meta[b*256 + ii];
            if ((meta & 15) == e) {
                int n = ch*256 + ii;
                if (c1 < CAP) {
                    d_slotTok[g*CAP + c1] = n;
                    d_a1[b*Nq + n] = (e << 10) | c1;
                } else d_a1[b*Nq + n] = -1;
                c1++;
            }
        }
    }
    int c1raw = c1;
    int pos = (c1 < CAP) ? c1 : CAP;
    for (int ch = 0; ch < 8; ++ch) {
        __syncthreads();
        for (int i = t; i < 2048; i += 64) {
            int bb = i >> 8, ii = i & 255;
            s_meta[i] = d_meta[bb*Nq + ch*256 + ii];
        }
        __syncthreads();
        for (int ii = 0; ii < 256; ++ii) {
            int meta = s_meta[b*256 + ii];
            if (((meta >> 4) & 15) == e) {
                int n = ch*256 + ii;
                if ((meta >> 8) & 1) {
                    if (pos < CAP) {
                        d_slotTok[g*CAP + pos] = n;
                        d_a2[b*Nq + n] = (e << 10) | pos;
                    } else d_a2[b*Nq + n] = -1;
                    pos++;
                } else d_a2[b*Nq + n] = -1;
            }
        }
    }
    s_red[t] = (d_proxy[b*Eq + e] / (float)Nq) * ((float)c1raw / (float)Nq);
    __syncthreads();
    if (t == 0) {
        float s = 0.f;
        for (int i = 0; i < 64; ++i) s += s_red[i];
        if ((size_t)out_size > OUT_MAIN) dout[OUT_MAIN] = s * 0.01f;
    }
}

// ---------------- dispatch: ei[g][c][:] = tf32(x[b][slotTok[g][c]][:]) into d_eo ----------------
__global__ __launch_bounds__(256) void dispatch_kernel(const float* __restrict__ x)
{
    const int idx = blockIdx.x;               // g*CAP + c
    const int g   = idx / CAP;
    const int b   = g & 7;
    const int tok = d_slotTok[idx];
    const int o   = threadIdx.x * 4;

    float4 v = make_float4(0.f, 0.f, 0.f, 0.f);
    if (tok >= 0) {
        v = *(const float4*)(x + ((size_t)(b*Nq) + tok) * Dq + o);
        v.x = tf32v(v.x); v.y = tf32v(v.y);
        v.z = tf32v(v.z); v.w = tf32v(v.w);
    }
    *(float4*)(d_eo + (size_t)idx * Dq + o) = v;
}

// ---------------- tf32 mma.sync grouped GEMM: CTA 128x256, warp 64x64, cp.async A ----------------
// 8 warps (2m x 4n), K in 32-chunks, 2-stage double buffer.
// SMEM: sA[2][16384] @0        (A[row(128)][k(32)], off=row*128+16*(slot^(row&7)))
//       sB[2][32768] @32768    (B[n(256)][k(32)],  same swizzle)
//       sBias @98304 (1KB)  -> total 99328
// A: pre-rounded contiguous rows (phase1: d_eo-as-ei, phase2: d_h) -> cp.async, no cvt.
// B: 32 coalesced scalar LDG + cvt + 8 STS.128 (transpose to n-major).
#define SMEM_FFN 99328
#define FFN_THREADS 256

template<int PHASE>
__global__ __launch_bounds__(FFN_THREADS, 1) void ffn_mma(const float* __restrict__ W,
                                                          const float* __restrict__ Bias)
{
    constexpr int Kdim  = (PHASE == 1) ? Dq : Hq;
    constexpr int Ncols = (PHASE == 1) ? Hq : Dq;
    constexpr int NCH   = Kdim / 32;

    extern __shared__ char smem[];
    float* sBias = (float*)(smem + 98304);

    const int tid  = threadIdx.x;
    const int wid  = tid >> 5, lane = tid & 31;
    const int g8   = lane >> 2, tg = lane & 3;
    const int n0   = blockIdx.x * 256;
    const int m0   = blockIdx.y * 128;
    const int grp  = blockIdx.z;
    const int e    = grp >> 3;
    const int wm   = wid & 1, wn = wid >> 1;       // 2m x 4n warps, 64x64 tiles
    const bool active = (m0 + wm*64) < CAP;        // skip all-padding 64-row slabs

    sBias[tid] = Bias[(size_t)e * Ncols + n0 + tid];
    __syncthreads();

    const uint32_t sb = smem_u32(smem);

    // A fill: row = tid>>1 (0..127), slots sbase..sbase+3 (sbase = (tid&1)*4)
    const int row   = tid >> 1;
    const int sbase = (tid & 1) * 4;
    const int crow  = (m0 + row < CAP) ? (m0 + row) : (CAP - 1);   // clamp padding rows in-bounds
    const float* Abase = (PHASE == 1) ? (const float*)d_eo : (const float*)d_h;
    const float* aRow  = Abase + ((size_t)grp * CAP + crow) * Kdim;
    uint32_t stRelA[4];
    #pragma unroll
    for (int i = 0; i < 4; ++i)
        stRelA[i] = (uint32_t)(row*128 + 16*((sbase + i) ^ (row & 7)));

    // B fill: bn = tid (0..255), slots 0..7
    const int bn = tid;
    const float* Wg = W + (size_t)e * Kdim * Ncols + n0;
    uint32_t stRelB[8];
    #pragma unroll
    for (int s = 0; s < 8; ++s)
        stRelB[s] = (uint32_t)(bn*128 + 16*(s ^ (bn & 7)));

    float4 rB[8];

    #define CPA(ch, buf) do { \
        const uint32_t so = sb + (uint32_t)((buf)*16384); \
        const float* asrc = aRow + (ch)*32 + sbase*4; \
        _Pragma("unroll") \
        for (int i = 0; i < 4; ++i) cpa16(so + stRelA[i], asrc + i*4); \
        CP_COMMIT(); \
    } while (0)
    #define LDB(ch) do { \
        _Pragma("unroll") \
        for (int s = 0; s < 8; ++s) { \
            const float* wp = Wg + (size_t)((ch)*32 + s*4) * Ncols + bn; \
            rB[s].x = wp[0]; \
            rB[s].y = wp[Ncols]; \
            rB[s].z = wp[(size_t)2*Ncols]; \
            rB[s].w = wp[(size_t)3*Ncols]; \
        } } while (0)
    #define STB(buf) do { \
        _Pragma("unroll") \
        for (int s = 0; s < 8; ++s) { \
            float4 v; \
            v.x = tf32v(rB[s].x); v.y = tf32v(rB[s].y); \
            v.z = tf32v(rB[s].z); v.w = tf32v(rB[s].w); \
            *(float4*)(smem + 32768 + (buf)*32768 + stRelB[s]) = v; \
        } } while (0)

    // ldmatrix geometry (validated r12)
    const int hiA = lane >> 4;
    const uint32_t aBaseRel = (uint32_t)(wm*64 + ((lane>>3)&1)*8 + (lane&7)) * 128u;
    const uint32_t bBaseRel = (uint32_t)(wn*64 + (lane>>4)*8 + (lane&7)) * 128u;
    uint32_t aSw[4], bSw[4];
    #pragma unroll
    for (int ks = 0; ks < 4; ++ks) {
        aSw[ks] = 16u * (uint32_t)((2*ks + hiA) ^ (lane & 7));
        bSw[ks] = 16u * (uint32_t)((2*ks + ((lane>>3)&1)) ^ (lane & 7));
    }

    float acc[4][8][4];
    #pragma unroll
    for (int mi = 0; mi < 4; ++mi)
        #pragma unroll
        for (int ni = 0; ni < 8; ++ni)
            #pragma unroll
            for (int q = 0; q < 4; ++q) acc[mi][ni][q] = 0.f;

    // prologue: stage chunk 0
    CPA(0, 0);
    LDB(0);
    STB(0);
    CP_WAIT0();
    __syncthreads();

    for (int ch = 0; ch < NCH; ++ch) {
        const int buf = ch & 1;
        if (ch + 1 < NCH) { CPA(ch + 1, buf ^ 1); LDB(ch + 1); }

        if (active) {
            const uint32_t aOff = sb + (uint32_t)(buf*16384);
            const uint32_t bOff = sb + 32768u + (uint32_t)(buf*32768);
            #pragma unroll
            for (int ks = 0; ks < 4; ++ks) {
                uint32_t af[4][4], bf[4][4];
                const uint32_t ao = aOff + aBaseRel + aSw[ks];
                const uint32_t bo = bOff + bBaseRel + bSw[ks];
                #pragma unroll
                for (int mi = 0; mi < 4; ++mi)
                    ldsm4(af[mi], ao + (uint32_t)(mi*2048));
                #pragma unroll
                for (int j = 0; j < 4; ++j)
                    ldsm4(bf[j], bo + (uint32_t)(j*2048));
                #pragma unroll
                for (int mi = 0; mi < 4; ++mi)
                    #pragma unroll
                    for (int j = 0; j < 4; ++j) {
                        mma_tf32(acc[mi][2*j],     af[mi], &bf[j][0]);
                        mma_tf32(acc[mi][2*j + 1], af[mi], &bf[j][2]);
                    }
            }
        }

        if (ch + 1 < NCH) STB(buf ^ 1);
        CP_WAIT0();
        __syncthreads();
    }
    #undef CPA
    #undef LDB
    #undef STB

    // epilogue: bias (+GELU phase1, tf32-round d_h so phase2 skips A-side cvt)
    float* Outp = (PHASE == 1) ? d_h : d_eo;
    #pragma unroll
    for (int mi = 0; mi < 4; ++mi) {
        #pragma unroll
        for (int h = 0; h < 2; ++h) {
            int c = m0 + wm*64 + mi*16 + g8 + h*8;
            if (c < CAP) {
                float* orow = Outp + ((size_t)grp*CAP + c) * Ncols + n0;
                #pragma unroll
                for (int ni = 0; ni < 8; ++ni) {
                    int col = wn*64 + ni*8 + 2*tg;
                    float v0 = acc[mi][ni][2*h]     + sBias[col];
                    float v1 = acc[mi][ni][2*h + 1] + sBias[col + 1];
                    if (PHASE == 1) {
                        v0 = 0.5f * v0 * (1.0f + erff(v0 * 0.70710678118654752f));
                        v1 = 0.5f * v1 * (1.0f + erff(v1 * 0.70710678118654752f));
                        v0 = tf32v(v0);
                        v1 = tf32v(v1);
                    }
                    float2 v = make_float2(v0, v1);
                    *(float2*)(orow + col) = v;
                }
            }
        }
    }
}

// ---------------- combine ----------------
__global__ __launch_bounds__(256) void combine_kernel(float* __restrict__ out)
{
    int tok = blockIdx.x;
    int b   = tok >> 11;
    int a1  = d_a1[tok], a2 = d_a2[tok];
    float g1 = d_g1[tok], g2 = d_g2[tok];
    int off = threadIdx.x * 4;

    float4 v = make_float4(0.f, 0.f, 0.f, 0.f);
    if (a1 >= 0) {
        size_t row = ((size_t)((a1 >> 10) * Bq + b)) * CAP + (a1 & 1023);
        const float4 s = *(const float4*)(d_eo + row * Dq + off);
        v.x = g1 * s.x; v.y = g1 * s.y; v.z = g1 * s.z; v.w = g1 * s.w;
    }
    if (a2 >= 0) {
        size_t row = ((size_t)((a2 >> 10) * Bq + b)) * CAP + (a2 & 1023);
        const float4 s = *(const float4*)(d_eo + row * Dq + off);
        v.x += g2 * s.x; v.y += g2 * s.y; v.z += g2 * s.z; v.w += g2 * s.w;
    }
    *(float4*)(out + (size_t)tok * Dq + off) = v;
}

// ---------------- launch ----------------
extern "C" void kernel_launch(void* const* d_in, const int* in_sizes, int n_in,
                              void* d_out, int out_size)
{
    const float* x  = (const float*)d_in[0];
    const float* wg = (const float*)d_in[1];
    const float* w1 = (const float*)d_in[2];
    const float* b1 = (const float*)d_in[3];
    const float* w2 = (const float*)d_in[4];
    const float* b2 = (const float*)d_in[5];
    const float* rp = (const float*)d_in[6];
    float* out = (float*)d_out;

    cudaFuncSetAttribute(ffn_mma<1>, cudaFuncAttributeMaxDynamicSharedMemorySize, SMEM_FFN);
    cudaFuncSetAttribute(ffn_mma<2>, cudaFuncAttributeMaxDynamicSharedMemorySize, SMEM_FFN);

    init_kernel<<<1, 64>>>();
    gating_kernel<<<NTOK/8, 256>>>(x, wg, rp);
    scan_kernel<<<1, 64>>>(out, out_size);
    dispatch_kernel<<<Eq*Bq*CAP, 256>>>(x);

    ffn_mma<1><<<dim3(Hq/256, 3, Eq*Bq), FFN_THREADS, SMEM_FFN>>>(w1, b1);
    ffn_mma<2><<<dim3(Dq/256, 3, Eq*Bq), FFN_THREADS, SMEM_FFN>>>(w2, b2);

    combine_kernel<<<NTOK, 256>>>(out);
}

// round 14
// speedup vs baseline: 1.0663x; 1.0663x over previous
#include <cuda_runtime.h>
#include <math.h>
#include <cstdint>

#define Bq   8
#define Nq   2048
#define Dq   1024
#define Eq   8
#define Hq   4096
#define CAP  320
#define NTOK (Bq*Nq)
#define OUT_MAIN ((size_t)NTOK*Dq)

// ---- scratch (round-5/12 set; no extra giant globals) ----
__device__ int   d_meta[NTOK];
__device__ float d_g1[NTOK];
__device__ float d_g2[NTOK];
__device__ int   d_a1[NTOK];
__device__ int   d_a2[NTOK];
__device__ float d_proxy[Bq*Eq];
__device__ int   d_slotTok[Eq*Bq*CAP];
__device__ float d_h [(size_t)Eq*Bq*CAP*Hq];   // tf32-valued post-GELU hidden
__device__ float d_eo[(size_t)Eq*Bq*CAP*Dq];

// ---------------- helpers ----------------
__device__ __forceinline__ uint32_t smem_u32(const void* p) {
    uint32_t a;
    asm("{ .reg .u64 t; cvta.to.shared.u64 t, %1; cvt.u32.u64 %0, t; }" : "=r"(a) : "l"(p));
    return a;
}
__device__ __forceinline__ uint32_t f2tf32(float x) {
    uint32_t r;
    asm("cvt.rna.tf32.f32 %0, %1;" : "=r"(r) : "f"(x));
    return r;
}
__device__ __forceinline__ float tf32v(float x) {
    return __uint_as_float(f2tf32(x));
}
__device__ __forceinline__ void mma_tf32(float* d, const uint32_t* a, const uint32_t* b) {
    asm volatile(
        "mma.sync.aligned.m16n8k8.row.col.f32.tf32.tf32.f32 "
        "{%0,%1,%2,%3}, {%4,%5,%6,%7}, {%8,%9}, {%0,%1,%2,%3};\n"
        : "+f"(d[0]), "+f"(d[1]), "+f"(d[2]), "+f"(d[3])
        : "r"(a[0]), "r"(a[1]), "r"(a[2]), "r"(a[3]), "r"(b[0]), "r"(b[1]));
}
__device__ __forceinline__ void ldsm4(uint32_t* r, uint32_t addr) {
    asm volatile("ldmatrix.sync.aligned.m8n8.x4.shared.b16 {%0,%1,%2,%3}, [%4];"
        : "=r"(r[0]), "=r"(r[1]), "=r"(r[2]), "=r"(r[3]) : "r"(addr));
}

// ---------------- init ----------------
__global__ void init_kernel() {
    int t = threadIdx.x;
    if (t < Bq*Eq) d_proxy[t] = 0.f;
}

// ---------------- gating ----------------
__global__ __launch_bounds__(256) void gating_kernel(
    const float* __restrict__ x, const float* __restrict__ wg,
    const float* __restrict__ rnd)
{
    __shared__ float s_wg[Eq][Dq];
    __shared__ float s_proxy[Eq];
    int tid = threadIdx.x;
    for (int f = tid; f < Dq*Eq; f += 256) {
        int d = f >> 3, e = f & 7;
        s_wg[e][d] = wg[f];
    }
    if (tid < Eq) s_proxy[tid] = 0.f;
    __syncthreads();

    int warp = tid >> 5, lane = tid & 31;
    int tok  = blockIdx.x * 8 + warp;
    const float* xp = x + (size_t)tok * Dq;

    float acc[Eq];
    #pragma unroll
    for (int e = 0; e < Eq; ++e) acc[e] = 0.f;
    #pragma unroll 4
    for (int i = 0; i < Dq/32; ++i) {
        float xv = xp[i*32 + lane];
        #pragma unroll
        for (int e = 0; e < Eq; ++e) acc[e] += xv * s_wg[e][i*32 + lane];
    }
    #pragma unroll
    for (int off = 16; off; off >>= 1)
        #pragma unroll
        for (int e = 0; e < Eq; ++e)
            acc[e] += __shfl_down_sync(0xffffffffu, acc[e], off);

    if (lane == 0) {
        float mx = acc[0];
        #pragma unroll
        for (int e = 1; e < Eq; ++e) mx = fmaxf(mx, acc[e]);
        float raw[Eq]; float s = 0.f;
        #pragma unroll
        for (int e = 0; e < Eq; ++e) { raw[e] = expf(acc[e] - mx); s += raw[e]; }
        float inv = 1.f / s;
        #pragma unroll
        for (int e = 0; e < Eq; ++e) raw[e] *= inv;
        int i1 = 0; float g1 = raw[0];
        #pragma unroll
        for (int e = 1; e < Eq; ++e) if (raw[e] > g1) { g1 = raw[e]; i1 = e; }
        int i2 = -1; float g2 = -1.f;
        #pragma unroll
        for (int e = 0; e < Eq; ++e) if (e != i1 && raw[e] > g2) { g2 = raw[e]; i2 = e; }
        float denom = g1 + g2 + 1e-9f;
        float g1n = g1 / denom, g2n = g2 / denom;
        int keep2 = (rnd[tok] < (g2n / 0.2f)) ? 1 : 0;
        d_meta[tok] = i1 | (i2 << 4) | (keep2 << 8);
        d_g1[tok] = g1n;
        d_g2[tok] = g2n;
        #pragma unroll
        for (int e = 0; e < Eq; ++e) atomicAdd(&s_proxy[e], raw[e]);
    }
    __syncthreads();
    if (tid < Eq) {
        int b = (blockIdx.x * 8) >> 11;
        atomicAdd(&d_proxy[b*Eq + tid], s_proxy[tid]);
    }
}

// ---------------- scan ----------------
__global__ void scan_kernel(float* __restrict__ dout, int out_size)
{
    __shared__ int   s_meta[2048];
    __shared__ float s_red[64];
    int t = threadIdx.x;
    int b = t >> 3, e = t & 7;
    int g = e * Bq + b;
    for (int j = 0; j < CAP; ++j) d_slotTok[g*CAP + j] = -1;
    int c1 = 0;
    for (int ch = 0; ch < 8; ++ch) {
        __syncthreads();
        for (int i = t; i < 2048; i += 64) {
            int bb = i >> 8, ii = i & 255;
            s_meta[i] = d_meta[bb*Nq + ch*256 + ii];
        }
        __syncthreads();
        for (int ii = 0; ii < 256; ++ii) {
            int meta = s_meta[b*256 + ii];
            if ((meta & 15) == e) {
                int n = ch*256 + ii;
                if (c1 < CAP) {
                    d_slotTok[g*CAP + c1] = n;
                    d_a1[b*Nq + n] = (e << 10) | c1;
                } else d_a1[b*Nq + n] = -1;
                c1++;
            }
        }
    }
    int c1raw = c1;
    int pos = (c1 < CAP) ? c1 : CAP;
    for (int ch = 0; ch < 8; ++ch) {
        __syncthreads();
        for (int i = t; i < 2048; i += 64) {
            int bb = i >> 8, ii = i & 255;
            s_meta[i] = d_meta[bb*Nq + ch*256 + ii];
        }
        __syncthreads();
        for (int ii = 0; ii < 256; ++ii) {
            int meta = s_meta[b*256 + ii];
            if (((meta >> 4) & 15) == e) {
                int n = ch*256 + ii;
                if ((meta >> 8) & 1) {
                    if (pos < CAP) {
                        d_slotTok[g*CAP + pos] = n;
                        d_a2[b*Nq + n] = (e << 10) | pos;
                    } else d_a2[b*Nq + n] = -1;
                    pos++;
                } else d_a2[b*Nq + n] = -1;
            }
        }
    }
    s_red[t] = (d_proxy[b*Eq + e] / (float)Nq) * ((float)c1raw / (float)Nq);
    __syncthreads();
    if (t == 0) {
        float s = 0.f;
        for (int i = 0; i < 64; ++i) s += s_red[i];
        if ((size_t)out_size > OUT_MAIN) dout[OUT_MAIN] = s * 0.01f;
    }
}

// ---------------- tf32 mma.sync grouped GEMM: CTA 128x256, warp 64x64, K-chunk 64 ----------------
// 8 warps (2m x 4n), 2-stage double buffer, staging split in halves interleaved with MMA halves.
// SMEM: sA[2][32768] @0        (A[row(128)][k(64)], row stride 256B, off=row*256+16*(slot^(row&7)))
//       sB[2][65536] @65536    (B[n(256)][k(64)],  same swizzle)
//       sPtr @196608 (1KB), sBias @197632 (1KB) -> total 198656
#define SMEM_FFN 198656
#define FFN_THREADS 256

template<int PHASE>
__global__ __launch_bounds__(FFN_THREADS, 1) void ffn_mma(const float* __restrict__ X,
                                                          const float* __restrict__ W,
                                                          const float* __restrict__ Bias)
{
    constexpr int Kdim  = (PHASE == 1) ? Dq : Hq;
    constexpr int Ncols = (PHASE == 1) ? Hq : Dq;
    constexpr int NCH   = Kdim / 64;

    extern __shared__ char smem[];
    const float** sPtr  = (const float**)(smem + 196608);
    float*        sBias = (float*)(smem + 197632);

    const int tid  = threadIdx.x;
    const int wid  = tid >> 5, lane = tid & 31;
    const int g8   = lane >> 2, tg = lane & 3;
    const int n0   = blockIdx.x * 256;
    const int m0   = blockIdx.y * 128;
    const int grp  = blockIdx.z;
    const int e    = grp >> 3, b = grp & 7;
    const int wm   = wid & 1, wn = wid >> 1;       // 2m x 4n warps, 64x64 tiles
    const bool active = (m0 + wm*64) < CAP;        // skip all-padding 64-row slabs

    if (tid < 128) {
        int c = m0 + tid;
        const float* p = nullptr;
        if (c < CAP) {
            if (PHASE == 1) {
                int tok = d_slotTok[grp*CAP + c];
                if (tok >= 0) p = X + ((size_t)(b*Nq) + tok) * Dq;
            } else {
                p = d_h + ((size_t)grp*CAP + c) * Hq;
            }
        }
        sPtr[tid] = p;
    }
    sBias[tid] = Bias[(size_t)e * Ncols + n0 + tid];
    __syncthreads();

    const uint32_t sb = smem_u32(smem);

    // A fill: arow = tid & 127 (one thread per row per k-half), ahalf = tid>>7 -> slots ahalf*8..+7
    const int arow  = tid & 127;
    const int ahalf = tid >> 7;
    const float* aRow = sPtr[arow];
    uint32_t stRelA[8];
    #pragma unroll
    for (int q = 0; q < 8; ++q)
        stRelA[q] = (uint32_t)(arow*256 + 16*((ahalf*8 + q) ^ (arow & 7)));

    // B fill: bn = tid (0..255), slots 0..15 in two halves of 8
    const int bn = tid;
    const float* Wg = W + (size_t)e * Kdim * Ncols + n0;
    uint32_t stRelB[16];
    #pragma unroll
    for (int s = 0; s < 16; ++s)
        stRelB[s] = (uint32_t)(bn*256 + 16*(s ^ (bn & 7)));

    float4 rA[4], rB[8];

    #define LDA_H(ch, h) do { \
        _Pragma("unroll") \
        for (int i = 0; i < 4; ++i) { \
            int q = (h)*4 + i; \
            if (aRow) rA[i] = *(const float4*)(aRow + (ch)*64 + (ahalf*8 + q)*4); \
            else      rA[i] = make_float4(0.f, 0.f, 0.f, 0.f); \
        } } while (0)
    #define STA_H(buf, h) do { \
        _Pragma("unroll") \
        for (int i = 0; i < 4; ++i) { \
            int q = (h)*4 + i; \
            float4 v = rA[i]; \
            if (PHASE == 1) { \
                v.x = tf32v(v.x); v.y = tf32v(v.y); \
                v.z = tf32v(v.z); v.w = tf32v(v.w); \
            } \
            *(float4*)(smem + (buf)*32768 + stRelA[q]) = v; \
        } } while (0)
    #define LDB_H(ch, h) do { \
        _Pragma("unroll") \
        for (int j = 0; j < 8; ++j) { \
            int s = (h)*8 + j; \
            const float* wp = Wg + (size_t)((ch)*64 + s*4) * Ncols + bn; \
            rB[j].x = wp[0]; \
            rB[j].y = wp[Ncols]; \
            rB[j].z = wp[(size_t)2*Ncols]; \
            rB[j].w = wp[(size_t)3*Ncols]; \
        } } while (0)
    #define STB_H(buf, h) do { \
        _Pragma("unroll") \
        for (int j = 0; j < 8; ++j) { \
            int s = (h)*8 + j; \
            float4 v; \
            v.x = tf32v(rB[j].x); v.y = tf32v(rB[j].y); \
            v.z = tf32v(rB[j].z); v.w = tf32v(rB[j].w); \
            *(float4*)(smem + 65536 + (buf)*65536 + stRelB[s]) = v; \
        } } while (0)

    // ldmatrix geometry (r12-validated pattern; row stride 256B, 16 slots/row)
    const int hiA = lane >> 4;
    const uint32_t aBaseRel = (uint32_t)(wm*64 + ((lane>>3)&1)*8 + (lane&7)) * 256u;
    const uint32_t bBaseRel = (uint32_t)(wn*64 + (lane>>4)*8 + (lane&7)) * 256u;
    uint32_t aSw[8], bSw[8];
    #pragma unroll
    for (int ks = 0; ks < 8; ++ks) {
        aSw[ks] = 16u * (uint32_t)((2*ks + hiA) ^ (lane & 7));
        bSw[ks] = 16u * (uint32_t)((2*ks + ((lane>>3)&1)) ^ (lane & 7));
    }

    float acc[4][8][4];
    #pragma unroll
    for (int mi = 0; mi < 4; ++mi)
        #pragma unroll
        for (int ni = 0; ni < 8; ++ni)
            #pragma unroll
            for (int q = 0; q < 4; ++q) acc[mi][ni][q] = 0.f;

    #define MMA_HALF(buf, h) do { \
        const uint32_t aOff = sb + (uint32_t)((buf)*32768); \
        const uint32_t bOff = sb + 65536u + (uint32_t)((buf)*65536); \
        _Pragma("unroll") \
        for (int ks = (h)*4; ks < (h)*4 + 4; ++ks) { \
            uint32_t af[4][4], bf[4][4]; \
            const uint32_t ao = aOff + aBaseRel + aSw[ks]; \
            const uint32_t bo = bOff + bBaseRel + bSw[ks]; \
            _Pragma("unroll") \
            for (int mi = 0; mi < 4; ++mi) \
                ldsm4(af[mi], ao + (uint32_t)(mi*4096)); \
            _Pragma("unroll") \
            for (int j = 0; j < 4; ++j) \
                ldsm4(bf[j], bo + (uint32_t)(j*4096)); \
            _Pragma("unroll") \
            for (int mi = 0; mi < 4; ++mi) \
                _Pragma("unroll") \
                for (int j = 0; j < 4; ++j) { \
                    mma_tf32(acc[mi][2*j],     af[mi], &bf[j][0]); \
                    mma_tf32(acc[mi][2*j + 1], af[mi], &bf[j][2]); \
                } \
        } } while (0)

    // prologue: stage chunk 0 fully
    LDA_H(0, 0); LDB_H(0, 0); STA_H(0, 0); STB_H(0, 0);
    LDA_H(0, 1); LDB_H(0, 1); STA_H(0, 1); STB_H(0, 1);
    __syncthreads();

    for (int ch = 0; ch < NCH; ++ch) {
        const int buf = ch & 1;
        if (ch + 1 < NCH) { LDA_H(ch + 1, 0); LDB_H(ch + 1, 0); }
        if (active) MMA_HALF(buf, 0);
        if (ch + 1 < NCH) {
            STA_H(buf ^ 1, 0); STB_H(buf ^ 1, 0);
            LDA_H(ch + 1, 1); LDB_H(ch + 1, 1);
        }
        if (active) MMA_HALF(buf, 1);
        if (ch + 1 < NCH) { STA_H(buf ^ 1, 1); STB_H(buf ^ 1, 1); }
        __syncthreads();
    }
    #undef LDA_H
    #undef STA_H
    #undef LDB_H
    #undef STB_H
    #undef MMA_HALF

    // epilogue: bias (+GELU phase1, tf32-round d_h so phase2 skips A-side cvt)
    float* Outp = (PHASE == 1) ? d_h : d_eo;
    #pragma unroll
    for (int mi = 0; mi < 4; ++mi) {
        #pragma unroll
        for (int h = 0; h < 2; ++h) {
            int c = m0 + wm*64 + mi*16 + g8 + h*8;
            if (c < CAP) {
                float* orow = Outp + ((size_t)grp*CAP + c) * Ncols + n0;
                #pragma unroll
                for (int ni = 0; ni < 8; ++ni) {
                    int col = wn*64 + ni*8 + 2*tg;
                    float v0 = acc[mi][ni][2*h]     + sBias[col];
                    float v1 = acc[mi][ni][2*h + 1] + sBias[col + 1];
                    if (PHASE == 1) {
                        v0 = 0.5f * v0 * (1.0f + erff(v0 * 0.70710678118654752f));
                        v1 = 0.5f * v1 * (1.0f + erff(v1 * 0.70710678118654752f));
                        v0 = tf32v(v0);
                        v1 = tf32v(v1);
                    }
                    float2 v = make_float2(v0, v1);
                    *(float2*)(orow + col) = v;
                }
            }
        }
    }
}

// ---------------- combine ----------------
__global__ __launch_bounds__(256) void combine_kernel(float* __restrict__ out)
{
    int tok = blockIdx.x;
    int b   = tok >> 11;
    int a1  = d_a1[tok], a2 = d_a2[tok];
    float g1 = d_g1[tok], g2 = d_g2[tok];
    int off = threadIdx.x * 4;

    float4 v = make_float4(0.f, 0.f, 0.f, 0.f);
    if (a1 >= 0) {
        size_t row = ((size_t)((a1 >> 10) * Bq + b)) * CAP + (a1 & 1023);
        const float4 s = *(const float4*)(d_eo + row * Dq + off);
        v.x = g1 * s.x; v.y = g1 * s.y; v.z = g1 * s.z; v.w = g1 * s.w;
    }
    if (a2 >= 0) {
        size_t row = ((size_t)((a2 >> 10) * Bq + b)) * CAP + (a2 & 1023);
        const float4 s = *(const float4*)(d_eo + row * Dq + off);
        v.x += g2 * s.x; v.y += g2 * s.y; v.z += g2 * s.z; v.w += g2 * s.w;
    }
    *(float4*)(out + (size_t)tok * Dq + off) = v;
}

// ---------------- launch ----------------
extern "C" void kernel_launch(void* const* d_in, const int* in_sizes, int n_in,
                              void* d_out, int out_size)
{
    const float* x  = (const float*)d_in[0];
    const float* wg = (const float*)d_in[1];
    const float* w1 = (const float*)d_in[2];
    const float* b1 = (const float*)d_in[3];
    const float* w2 = (const float*)d_in[4];
    const float* b2 = (const float*)d_in[5];
    const float* rp = (const float*)d_in[6];
    float* out = (float*)d_out;

    cudaFuncSetAttribute(ffn_mma<1>, cudaFuncAttributeMaxDynamicSharedMemorySize, SMEM_FFN);
    cudaFuncSetAttribute(ffn_mma<2>, cudaFuncAttributeMaxDynamicSharedMemorySize, SMEM_FFN);

    init_kernel<<<1, 64>>>();
    gating_kernel<<<NTOK/8, 256>>>(x, wg, rp);
    scan_kernel<<<1, 64>>>(out, out_size);

    ffn_mma<1><<<dim3(Hq/256, 3, Eq*Bq), FFN_THREADS, SMEM_FFN>>>(x, w1, b1);
    ffn_mma<2><<<dim3(Dq/256, 3, Eq*Bq), FFN_THREADS, SMEM_FFN>>>(d_h, w2, b2);

    combine_kernel<<<NTOK, 256>>>(out);
}

// round 15
// speedup vs baseline: 1.5716x; 1.4739x over previous
#include <cuda_runtime.h>
#include <cuda_fp16.h>
#include <math.h>
#include <cstdint>

#define Bq   8
#define Nq   2048
#define Dq   1024
#define Eq   8
#define Hq   4096
#define CAP  320
#define NTOK (Bq*Nq)
#define OUT_MAIN ((size_t)NTOK*Dq)

// ---- scratch (round-5/12 set; d_h now holds fp16 payload in its first half) ----
__device__ int   d_meta[NTOK];
__device__ float d_g1[NTOK];
__device__ float d_g2[NTOK];
__device__ int   d_a1[NTOK];
__device__ int   d_a2[NTOK];
__device__ float d_proxy[Bq*Eq];
__device__ int   d_slotTok[Eq*Bq*CAP];
__device__ float d_h [(size_t)Eq*Bq*CAP*Hq];   // reinterpreted as __half[...]
__device__ float d_eo[(size_t)Eq*Bq*CAP*Dq];

// ---------------- helpers ----------------
__device__ __forceinline__ uint32_t smem_u32(const void* p) {
    uint32_t a;
    asm("{ .reg .u64 t; cvta.to.shared.u64 t, %1; cvt.u32.u64 %0, t; }" : "=r"(a) : "l"(p));
    return a;
}
__device__ __forceinline__ uint32_t packh2(float lo, float hi) {
    uint32_t r;
    asm("cvt.rn.f16x2.f32 %0, %1, %2;" : "=r"(r) : "f"(hi), "f"(lo));
    return r;
}
__device__ __forceinline__ void mma_fp16(float* d, const uint32_t* a, const uint32_t* b) {
    asm volatile(
        "mma.sync.aligned.m16n8k16.row.col.f32.f16.f16.f32 "
        "{%0,%1,%2,%3}, {%4,%5,%6,%7}, {%8,%9}, {%0,%1,%2,%3};\n"
        : "+f"(d[0]), "+f"(d[1]), "+f"(d[2]), "+f"(d[3])
        : "r"(a[0]), "r"(a[1]), "r"(a[2]), "r"(a[3]), "r"(b[0]), "r"(b[1]));
}
__device__ __forceinline__ void ldsm4(uint32_t* r, uint32_t addr) {
    asm volatile("ldmatrix.sync.aligned.m8n8.x4.shared.b16 {%0,%1,%2,%3}, [%4];"
        : "=r"(r[0]), "=r"(r[1]), "=r"(r[2]), "=r"(r[3]) : "r"(addr));
}

// ---------------- init ----------------
__global__ void init_kernel() {
    int t = threadIdx.x;
    if (t < Bq*Eq) d_proxy[t] = 0.f;
}

// ---------------- gating ----------------
__global__ __launch_bounds__(256) void gating_kernel(
    const float* __restrict__ x, const float* __restrict__ wg,
    const float* __restrict__ rnd)
{
    __shared__ float s_wg[Eq][Dq];
    __shared__ float s_proxy[Eq];
    int tid = threadIdx.x;
    for (int f = tid; f < Dq*Eq; f += 256) {
        int d = f >> 3, e = f & 7;
        s_wg[e][d] = wg[f];
    }
    if (tid < Eq) s_proxy[tid] = 0.f;
    __syncthreads();

    int warp = tid >> 5, lane = tid & 31;
    int tok  = blockIdx.x * 8 + warp;
    const float* xp = x + (size_t)tok * Dq;

    float acc[Eq];
    #pragma unroll
    for (int e = 0; e < Eq; ++e) acc[e] = 0.f;
    #pragma unroll 4
    for (int i = 0; i < Dq/32; ++i) {
        float xv = xp[i*32 + lane];
        #pragma unroll
        for (int e = 0; e < Eq; ++e) acc[e] += xv * s_wg[e][i*32 + lane];
    }
    #pragma unroll
    for (int off = 16; off; off >>= 1)
        #pragma unroll
        for (int e = 0; e < Eq; ++e)
            acc[e] += __shfl_down_sync(0xffffffffu, acc[e], off);

    if (lane == 0) {
        float mx = acc[0];
        #pragma unroll
        for (int e = 1; e < Eq; ++e) mx = fmaxf(mx, acc[e]);
        float raw[Eq]; float s = 0.f;
        #pragma unroll
        for (int e = 0; e < Eq; ++e) { raw[e] = expf(acc[e] - mx); s += raw[e]; }
        float inv = 1.f / s;
        #pragma unroll
        for (int e = 0; e < Eq; ++e) raw[e] *= inv;
        int i1 = 0; float g1 = raw[0];
        #pragma unroll
        for (int e = 1; e < Eq; ++e) if (raw[e] > g1) { g1 = raw[e]; i1 = e; }
        int i2 = -1; float g2 = -1.f;
        #pragma unroll
        for (int e = 0; e < Eq; ++e) if (e != i1 && raw[e] > g2) { g2 = raw[e]; i2 = e; }
        float denom = g1 + g2 + 1e-9f;
        float g1n = g1 / denom, g2n = g2 / denom;
        int keep2 = (rnd[tok] < (g2n / 0.2f)) ? 1 : 0;
        d_meta[tok] = i1 | (i2 << 4) | (keep2 << 8);
        d_g1[tok] = g1n;
        d_g2[tok] = g2n;
        #pragma unroll
        for (int e = 0; e < Eq; ++e) atomicAdd(&s_proxy[e], raw[e]);
    }
    __syncthreads();
    if (tid < Eq) {
        int b = (blockIdx.x * 8) >> 11;
        atomicAdd(&d_proxy[b*Eq + tid], s_proxy[tid]);
    }
}

// ---------------- scan ----------------
__global__ void scan_kernel(float* __restrict__ dout, int out_size)
{
    __shared__ int   s_meta[2048];
    __shared__ float s_red[64];
    int t = threadIdx.x;
    int b = t >> 3, e = t & 7;
    int g = e * Bq + b;
    for (int j = 0; j < CAP; ++j) d_slotTok[g*CAP + j] = -1;
    int c1 = 0;
    for (int ch = 0; ch < 8; ++ch) {
        __syncthreads();
        for (int i = t; i < 2048; i += 64) {
            int bb = i >> 8, ii = i & 255;
            s_meta[i] = d_meta[bb*Nq + ch*256 + ii];
        }
        __syncthreads();
        for (int ii = 0; ii < 256; ++ii) {
            int meta = s_meta[b*256 + ii];
            if ((meta & 15) == e) {
                int n = ch*256 + ii;
                if (c1 < CAP) {
                    d_slotTok[g*CAP + c1] = n;
                    d_a1[b*Nq + n] = (e << 10) | c1;
                } else d_a1[b*Nq + n] = -1;
                c1++;
            }
        }
    }
    int c1raw = c1;
    int pos = (c1 < CAP) ? c1 : CAP;
    for (int ch = 0; ch < 8; ++ch) {
        __syncthreads();
        for (int i = t; i < 2048; i += 64) {
            int bb = i >> 8, ii = i & 255;
            s_meta[i] = d_meta[bb*Nq + ch*256 + ii];
        }
        __syncthreads();
        for (int ii = 0; ii < 256; ++ii) {
            int meta = s_meta[b*256 + ii];
            if (((meta >> 4) & 15) == e) {
                int n = ch*256 + ii;
                if ((meta >> 8) & 1) {
                    if (pos < CAP) {
                        d_slotTok[g*CAP + pos] = n;
                        d_a2[b*Nq + n] = (e << 10) | pos;
                    } else d_a2[b*Nq + n] = -1;
                    pos++;
                } else d_a2[b*Nq + n] = -1;
            }
        }
    }
    s_red[t] = (d_proxy[b*Eq + e] / (float)Nq) * ((float)c1raw / (float)Nq);
    __syncthreads();
    if (t == 0) {
        float s = 0.f;
        for (int i = 0; i < 64; ++i) s += s_red[i];
        if ((size_t)out_size > OUT_MAIN) dout[OUT_MAIN] = s * 0.01f;
    }
}

// ---------------- fp16 mma.sync grouped GEMM: CTA 128x256, warp 64x64, K-chunk 64 ----------------
// 8 warps (2m x 4n), mma m16n8k16, 2-stage double buffer, half-split staging.
// SMEM: sA[2][16384] @0       (A[row(128)][k(64) half], 128B rows, off=row*128+16*(slot^(row&7)))
//       sB[2][32768] @32768   (B[n(256)][k(64) half], same swizzle)
//       sPtr @98304 (1KB), sBias @99328 (1KB) -> total 100352
// A: fp32 x gathered+cvt (phase1) or fp16 d_h pure copy (phase2).
// B: 32 coalesced scalar fp32 LDG per half + cvt.f16x2 + STS.128.
#define SMEM_FFN 100352
#define FFN_THREADS 256

template<int PHASE>
__global__ __launch_bounds__(FFN_THREADS, 1) void ffn_mma(const float* __restrict__ X,
                                                          const float* __restrict__ W,
                                                          const float* __restrict__ Bias)
{
    constexpr int Kdim  = (PHASE == 1) ? Dq : Hq;
    constexpr int Ncols = (PHASE == 1) ? Hq : Dq;
    constexpr int NCH   = Kdim / 64;

    extern __shared__ char smem[];
    const void** sPtr   = (const void**)(smem + 98304);
    float*       sBias  = (float*)(smem + 99328);

    const int tid  = threadIdx.x;
    const int wid  = tid >> 5, lane = tid & 31;
    const int g8   = lane >> 2, tg = lane & 3;
    const int n0   = blockIdx.x * 256;
    const int m0   = blockIdx.y * 128;
    const int grp  = blockIdx.z;
    const int e    = grp >> 3, b = grp & 7;
    const int wm   = wid & 1, wn = wid >> 1;       // 2m x 4n warps, 64x64 tiles
    const bool active = (m0 + wm*64) < CAP;        // skip all-padding 64-row slabs

    if (tid < 128) {
        int c = m0 + tid;
        const void* p = nullptr;
        if (c < CAP) {
            if (PHASE == 1) {
                int tok = d_slotTok[grp*CAP + c];
                if (tok >= 0) p = X + ((size_t)(b*Nq) + tok) * Dq;
            } else {
                p = (const __half*)d_h + ((size_t)grp*CAP + c) * Hq;
            }
        }
        sPtr[tid] = p;
    }
    sBias[tid] = Bias[(size_t)e * Ncols + n0 + tid];
    __syncthreads();

    const uint32_t sb = smem_u32(smem);

    // A fill: arow = tid & 127, ahalf = tid >> 7; thread's slots per k-half h: h*4 + ahalf*2 + {0,1}
    const int arow  = tid & 127;
    const int ahalf = tid >> 7;
    const void* aPtr = sPtr[arow];
    uint32_t stRelA[4];                 // index 2h+i
    #pragma unroll
    for (int h = 0; h < 2; ++h)
        #pragma unroll
        for (int i = 0; i < 2; ++i) {
            int sl = h*4 + ahalf*2 + i;
            stRelA[2*h + i] = (uint32_t)(arow*128 + 16*(sl ^ (arow & 7)));
        }

    // B fill: bn = tid (0..255), slots 0..7 (slot = 8 k-halves = 16B)
    const int bn = tid;
    const float* Wg = W + (size_t)e * Kdim * Ncols + n0;
    uint32_t stRelB[8];
    #pragma unroll
    for (int s = 0; s < 8; ++s)
        stRelB[s] = (uint32_t)(bn*128 + 16*(s ^ (bn & 7)));

    float4 rA4[4];      // phase1 staging (2 slots x 8 floats)
    uint4  rAh[2];      // phase2 staging (2 slots x 16B fp16)
    float  rb[32];      // B staging per half

    #define LDA_H(ch, h) do { \
        if (PHASE == 1) { \
            _Pragma("unroll") \
            for (int i = 0; i < 2; ++i) { \
                int sl = (h)*4 + ahalf*2 + i; \
                if (aPtr) { \
                    const float* p = (const float*)aPtr + (ch)*64 + sl*8; \
                    rA4[2*i]   = *(const float4*)(p); \
                    rA4[2*i+1] = *(const float4*)(p + 4); \
                } else { \
                    rA4[2*i] = rA4[2*i+1] = make_float4(0.f, 0.f, 0.f, 0.f); \
                } \
            } \
        } else { \
            _Pragma("unroll") \
            for (int i = 0; i < 2; ++i) { \
                int sl = (h)*4 + ahalf*2 + i; \
                if (aPtr) rAh[i] = *(const uint4*)((const __half*)aPtr + (ch)*64 + sl*8); \
                else      rAh[i] = make_uint4(0u, 0u, 0u, 0u); \
            } \
        } } while (0)
    #define STA_H(buf, h) do { \
        _Pragma("unroll") \
        for (int i = 0; i < 2; ++i) { \
            uint4 q; \
            if (PHASE == 1) { \
                q.x = packh2(rA4[2*i].x,   rA4[2*i].y); \
                q.y = packh2(rA4[2*i].z,   rA4[2*i].w); \
                q.z = packh2(rA4[2*i+1].x, rA4[2*i+1].y); \
                q.w = packh2(rA4[2*i+1].z, rA4[2*i+1].w); \
            } else { \
                q = rAh[i]; \
            } \
            *(uint4*)(smem + (buf)*16384 + stRelA[2*(h) + i]) = q; \
        } } while (0)
    #define LDB_H(ch, h) do { \
        _Pragma("unroll") \
        for (int j4 = 0; j4 < 4; ++j4) { \
            int sl = (h)*4 + j4; \
            const float* wp = Wg + (size_t)((ch)*64 + sl*8) * Ncols + bn; \
            _Pragma("unroll") \
            for (int r = 0; r < 8; ++r) \
                rb[j4*8 + r] = wp[(size_t)r * Ncols]; \
        } } while (0)
    #define STB_H(buf, h) do { \
        _Pragma("unroll") \
        for (int j4 = 0; j4 < 4; ++j4) { \
            uint4 q; \
            q.x = packh2(rb[j4*8+0], rb[j4*8+1]); \
            q.y = packh2(rb[j4*8+2], rb[j4*8+3]); \
            q.z = packh2(rb[j4*8+4], rb[j4*8+5]); \
            q.w = packh2(rb[j4*8+6], rb[j4*8+7]); \
            *(uint4*)(smem + 32768 + (buf)*32768 + stRelB[(h)*4 + j4]) = q; \
        } } while (0)

    // ldmatrix geometry (byte-identical to r12-validated pattern; 8 slots/row, 128B rows)
    const int hiA = lane >> 4;
    const uint32_t aBaseRel = (uint32_t)(wm*64 + ((lane>>3)&1)*8 + (lane&7)) * 128u;
    const uint32_t bBaseRel = (uint32_t)(wn*64 + (lane>>4)*8 + (lane&7)) * 128u;
    uint32_t aSw[4], bSw[4];
    #pragma unroll
    for (int ks = 0; ks < 4; ++ks) {
        aSw[ks] = 16u * (uint32_t)((2*ks + hiA) ^ (lane & 7));
        bSw[ks] = 16u * (uint32_t)((2*ks + ((lane>>3)&1)) ^ (lane & 7));
    }

    float acc[4][8][4];
    #pragma unroll
    for (int mi = 0; mi < 4; ++mi)
        #pragma unroll
        for (int ni = 0; ni < 8; ++ni)
            #pragma unroll
            for (int q = 0; q < 4; ++q) acc[mi][ni][q] = 0.f;

    #define MMA_HALF(buf, h) do { \
        const uint32_t aOff = sb + (uint32_t)((buf)*16384); \
        const uint32_t bOff = sb + 32768u + (uint32_t)((buf)*32768); \
        _Pragma("unroll") \
        for (int ks = (h)*2; ks < (h)*2 + 2; ++ks) { \
            uint32_t af[4][4], bf[4][4]; \
            const uint32_t ao = aOff + aBaseRel + aSw[ks]; \
            const uint32_t bo = bOff + bBaseRel + bSw[ks]; \
            _Pragma("unroll") \
            for (int mi = 0; mi < 4; ++mi) \
                ldsm4(af[mi], ao + (uint32_t)(mi*2048)); \
            _Pragma("unroll") \
            for (int j = 0; j < 4; ++j) \
                ldsm4(bf[j], bo + (uint32_t)(j*2048)); \
            _Pragma("unroll") \
            for (int mi = 0; mi < 4; ++mi) \
                _Pragma("unroll") \
                for (int j = 0; j < 4; ++j) { \
                    mma_fp16(acc[mi][2*j],     af[mi], &bf[j][0]); \
                    mma_fp16(acc[mi][2*j + 1], af[mi], &bf[j][2]); \
                } \
        } } while (0)

    // prologue: stage chunk 0 fully
    LDA_H(0, 0); LDB_H(0, 0); STA_H(0, 0); STB_H(0, 0);
    LDA_H(0, 1); LDB_H(0, 1); STA_H(0, 1); STB_H(0, 1);
    __syncthreads();

    for (int ch = 0; ch < NCH; ++ch) {
        const int buf = ch & 1;
        if (ch + 1 < NCH) { LDA_H(ch + 1, 0); LDB_H(ch + 1, 0); }
        if (active) MMA_HALF(buf, 0);
        if (ch + 1 < NCH) {
            STA_H(buf ^ 1, 0); STB_H(buf ^ 1, 0);
            LDA_H(ch + 1, 1); LDB_H(ch + 1, 1);
        }
        if (active) MMA_HALF(buf, 1);
        if (ch + 1 < NCH) { STA_H(buf ^ 1, 1); STB_H(buf ^ 1, 1); }
        __syncthreads();
    }
    #undef LDA_H
    #undef STA_H
    #undef LDB_H
    #undef STB_H
    #undef MMA_HALF

    // epilogue: bias (+GELU phase1 -> fp16 d_h; phase2 -> fp32 d_eo)
    #pragma unroll
    for (int mi = 0; mi < 4; ++mi) {
        #pragma unroll
        for (int h = 0; h < 2; ++h) {
            int c = m0 + wm*64 + mi*16 + g8 + h*8;
            if (c < CAP) {
                #pragma unroll
                for (int ni = 0; ni < 8; ++ni) {
                    int col = wn*64 + ni*8 + 2*tg;
                    float v0 = acc[mi][ni][2*h]     + sBias[col];
                    float v1 = acc[mi][ni][2*h + 1] + sBias[col + 1];
                    if (PHASE == 1) {
                        v0 = 0.5f * v0 * (1.0f + erff(v0 * 0.70710678118654752f));
                        v1 = 0.5f * v1 * (1.0f + erff(v1 * 0.70710678118654752f));
                        __half* orowH = (__half*)d_h + ((size_t)grp*CAP + c) * Hq + n0;
                        *(uint32_t*)(orowH + col) = packh2(v0, v1);
                    } else {
                        float* orow = d_eo + ((size_t)grp*CAP + c) * Dq + n0;
                        float2 v = make_float2(v0, v1);
                        *(float2*)(orow + col) = v;
                    }
                }
            }
        }
    }
}

// ---------------- combine ----------------
__global__ __launch_bounds__(256) void combine_kernel(float* __restrict__ out)
{
    int tok = blockIdx.x;
    int b   = tok >> 11;
    int a1  = d_a1[tok], a2 = d_a2[tok];
    float g1 = d_g1[tok], g2 = d_g2[tok];
    int off = threadIdx.x * 4;

    float4 v = make_float4(0.f, 0.f, 0.f, 0.f);
    if (a1 >= 0) {
        size_t row = ((size_t)((a1 >> 10) * Bq + b)) * CAP + (a1 & 1023);
        const float4 s = *(const float4*)(d_eo + row * Dq + off);
        v.x = g1 * s.x; v.y = g1 * s.y; v.z = g1 * s.z; v.w = g1 * s.w;
    }
    if (a2 >= 0) {
        size_t row = ((size_t)((a2 >> 10) * Bq + b)) * CAP + (a2 & 1023);
        const float4 s = *(const float4*)(d_eo + row * Dq + off);
        v.x += g2 * s.x; v.y += g2 * s.y; v.z += g2 * s.z; v.w += g2 * s.w;
    }
    *(float4*)(out + (size_t)tok * Dq + off) = v;
}

// ---------------- launch ----------------
extern "C" void kernel_launch(void* const* d_in, const int* in_sizes, int n_in,
                              void* d_out, int out_size)
{
    const float* x  = (const float*)d_in[0];
    const float* wg = (const float*)d_in[1];
    const float* w1 = (const float*)d_in[2];
    const float* b1 = (const float*)d_in[3];
    const float* w2 = (const float*)d_in[4];
    const float* b2 = (const float*)d_in[5];
    const float* rp = (const float*)d_in[6];
    float* out = (float*)d_out;

    cudaFuncSetAttribute(ffn_mma<1>, cudaFuncAttributeMaxDynamicSharedMemorySize, SMEM_FFN);
    cudaFuncSetAttribute(ffn_mma<2>, cudaFuncAttributeMaxDynamicSharedMemorySize, SMEM_FFN);

    init_kernel<<<1, 64>>>();
    gating_kernel<<<NTOK/8, 256>>>(x, wg, rp);
    scan_kernel<<<1, 64>>>(out, out_size);

    ffn_mma<1><<<dim3(Hq/256, 3, Eq*Bq), FFN_THREADS, SMEM_FFN>>>(x, w1, b1);
    ffn_mma<2><<<dim3(Dq/256, 3, Eq*Bq), FFN_THREADS, SMEM_FFN>>>(nullptr, w2, b2);

    combine_kernel<<<NTOK, 256>>>(out);
}